// round 2
// baseline (speedup 1.0000x reference)
#include <cuda_runtime.h>
#include <cstddef>

#define BB 2048
#define NN 512
#define XX 32
#define HH 64
#define TILE_B 16
#define THREADS 512
#define NBLK (BB / TILE_B)   /* 128 */
#define HPITCH 20            /* padded row pitch (floats), 80B, 16B aligned */
#define GPITCH 65            /* g_sh pad to break bank conflicts */

__device__ __forceinline__ unsigned long long pack2(float v) {
    unsigned long long r;
    asm("mov.b64 %0, {%1, %1};" : "=l"(r) : "f"(v));
    return r;
}
__device__ __forceinline__ unsigned long long fma2(unsigned long long a,
                                                   unsigned long long b,
                                                   unsigned long long c) {
    unsigned long long d;
    asm("fma.rn.f32x2 %0, %1, %2, %3;" : "=l"(d) : "l"(a), "l"(b), "l"(c));
    return d;
}
__device__ __forceinline__ unsigned long long add2(unsigned long long a,
                                                   unsigned long long b) {
    unsigned long long d;
    asm("add.rn.f32x2 %0, %1, %2;" : "=l"(d) : "l"(a), "l"(b));
    return d;
}
__device__ __forceinline__ void unpack2(unsigned long long v, float& lo, float& hi) {
    asm("mov.b64 {%0, %1}, %2;" : "=f"(lo), "=f"(hi) : "l"(v));
}

__device__ __forceinline__ float sigmoidf_fast(float x) {
    return __fdividef(1.0f, 1.0f + __expf(-x));
}
__device__ __forceinline__ float tanhf_fast(float x) {
    return __fdividef(2.0f, 1.0f + __expf(-2.0f * x)) - 1.0f;
}

__global__ void __launch_bounds__(THREADS, 1)
timelstm_kernel(const float* __restrict__ x,
                const float* __restrict__ ig_w_c, const float* __restrict__ ig_w_h,
                const float* __restrict__ ig_w_x, const float* __restrict__ ig_b,
                const float* __restrict__ fg_w_c, const float* __restrict__ fg_w_h,
                const float* __restrict__ fg_w_x, const float* __restrict__ fg_b,
                const float* __restrict__ in_w_h, const float* __restrict__ in_w_x,
                const float* __restrict__ in_b,
                const float* __restrict__ og_w_cn, const float* __restrict__ og_w_h,
                const float* __restrict__ og_w_x, const float* __restrict__ og_b,
                float* __restrict__ out)
{
    // h_sh/x_sh: [k][row], padded pitch, 16B-aligned 64B row-runs for LDS.128.
    __shared__ __align__(16) float h_sh[HH * HPITCH];
    __shared__ __align__(16) float x_sh[XX * HPITCH];
    __shared__ float g_sh[4][TILE_B][GPITCH];   // gate pre-activations
    __shared__ float cm_sh[TILE_B][HH];
    __shared__ float wc_sh[3][HH];              // ig_w_c, fg_w_c, og_w_cn

    const int tid  = threadIdx.x;
    const int b0   = blockIdx.x * TILE_B;
    const int w    = tid & 1;           // k-slice 0/1 (adjacent lanes)
    const int hid  = (tid >> 1) & 63;   // output channel
    const int gate = tid >> 7;          // 0..3 : ig, fg, in, og

    // ---- per-thread HALF weight rows into registers ----
    const float* Wh; const float* Wx; const float* Bv;
    if (gate == 0)      { Wh = ig_w_h; Wx = ig_w_x; Bv = ig_b; }
    else if (gate == 1) { Wh = fg_w_h; Wx = fg_w_x; Bv = fg_b; }
    else if (gate == 2) { Wh = in_w_h; Wx = in_w_x; Bv = in_b; }
    else                { Wh = og_w_h; Wx = og_w_x; Bv = og_b; }

    float wh[32], wx[16];
    #pragma unroll
    for (int j = 0; j < 32; j++) wh[j] = Wh[hid * HH + w * 32 + j];
    #pragma unroll
    for (int j = 0; j < 16; j++) wx[j] = Wx[hid * XX + w * 16 + j];
    const float bias = (w == 0) ? Bv[hid] : 0.0f;

    if (tid < HH) {
        wc_sh[0][tid] = ig_w_c[tid];
        wc_sh[1][tid] = fg_w_c[tid];
        wc_sh[2][tid] = og_w_cn[tid];
    }
    for (int i = tid; i < HH * HPITCH; i += THREADS) h_sh[i] = 0.0f;
    for (int i = tid; i < TILE_B * HH; i += THREADS) (&cm_sh[0][0])[i] = 0.0f;

    // ---- x prefetch: one value per thread per step (512 = 16 rows x 32 k) ----
    const int xr = tid >> 5;   // row 0..15
    const int xk = tid & 31;   // k   0..31
    const float* xptr = x + ((size_t)(b0 + xr) * NN) * XX + xk;
    float xv = xptr[0];

    // phase-B mapping (fixed per thread)
    const int bh = tid & 63;       // channel
    const int br = tid >> 6;       // row 0..7 (also does br+8)

    for (int t = 0; t < NN; t++) {
        // deposit prefetched x_t
        x_sh[xk * HPITCH + xr] = xv;
        __syncthreads();   // x_sh ready AND previous phase-B h/cm writes visible

        // prefetch x_{t+1}
        if (t + 1 < NN) xv = xptr[(size_t)(t + 1) * XX];

        // ---- phase A: half-dot-products, 16 rows packed as 8 f32x2 ----
        unsigned long long acc[8];
        {
            unsigned long long b2 = pack2(bias);
            #pragma unroll
            for (int i = 0; i < 8; i++) acc[i] = b2;
        }
        #pragma unroll
        for (int j = 0; j < 16; j++) {
            unsigned long long w2 = pack2(wx[j]);
            const ulonglong2* p =
                reinterpret_cast<const ulonglong2*>(&x_sh[(w * 16 + j) * HPITCH]);
            #pragma unroll
            for (int q = 0; q < 4; q++) {
                ulonglong2 v = p[q];
                acc[2 * q]     = fma2(v.x, w2, acc[2 * q]);
                acc[2 * q + 1] = fma2(v.y, w2, acc[2 * q + 1]);
            }
        }
        #pragma unroll
        for (int j = 0; j < 32; j++) {
            unsigned long long w2 = pack2(wh[j]);
            const ulonglong2* p =
                reinterpret_cast<const ulonglong2*>(&h_sh[(w * 32 + j) * HPITCH]);
            #pragma unroll
            for (int q = 0; q < 4; q++) {
                ulonglong2 v = p[q];
                acc[2 * q]     = fma2(v.x, w2, acc[2 * q]);
                acc[2 * q + 1] = fma2(v.y, w2, acc[2 * q + 1]);
            }
        }
        // ---- k-slice reduce: partner is adjacent lane ----
        #pragma unroll
        for (int i = 0; i < 8; i++) {
            unsigned long long o = __shfl_xor_sync(0xffffffffu, acc[i], 1);
            acc[i] = add2(acc[i], o);
        }
        // slice w writes rows [8w, 8w+8)
        #pragma unroll
        for (int i = 0; i < 4; i++) {
            float lo, hi;
            unpack2(acc[w * 4 + i], lo, hi);
            g_sh[gate][w * 8 + 2 * i][hid]     = lo;
            g_sh[gate][w * 8 + 2 * i + 1][hid] = hi;
        }
        __syncthreads();   // g_sh ready; phase A done reading h_sh/x_sh

        // ---- phase B: activations + state update (2 elements per thread) ----
        {
            const float wic = wc_sh[0][bh];
            const float wfc = wc_sh[1][bh];
            const float woc = wc_sh[2][bh];
            #pragma unroll
            for (int e = 0; e < 2; e++) {
                const int r = br + 8 * e;
                const float cm  = cm_sh[r][bh];
                const float ig  = sigmoidf_fast(wic * cm + g_sh[0][r][bh]);
                const float fg  = sigmoidf_fast(wfc * cm + g_sh[1][r][bh]);
                const float inn = tanhf_fast(g_sh[2][r][bh]);
                const float cmn = fg * cm + ig * inn;
                const float og  = sigmoidf_fast(woc * cmn + g_sh[3][r][bh]);
                const float hv  = og * tanhf_fast(cmn);
                cm_sh[r][bh] = cmn;
                h_sh[bh * HPITCH + r] = hv;
                if (t == NN - 1)
                    out[(size_t)(b0 + r) * HH + bh] = hv;
            }
        }
        // no barrier here: next x_sh deposit is a different array; the loop-top
        // barrier orders h_sh/cm/g writes before the next phase A.
    }
}

extern "C" void kernel_launch(void* const* d_in, const int* in_sizes, int n_in,
                              void* d_out, int out_size) {
    const float* x       = (const float*)d_in[0];
    const float* ig_w_c  = (const float*)d_in[1];
    const float* ig_w_h  = (const float*)d_in[2];
    const float* ig_w_x  = (const float*)d_in[3];
    const float* ig_b    = (const float*)d_in[4];
    const float* fg_w_c  = (const float*)d_in[5];
    const float* fg_w_h  = (const float*)d_in[6];
    const float* fg_w_x  = (const float*)d_in[7];
    const float* fg_b    = (const float*)d_in[8];
    const float* in_w_h  = (const float*)d_in[9];
    const float* in_w_x  = (const float*)d_in[10];
    const float* in_b    = (const float*)d_in[11];
    const float* og_w_cn = (const float*)d_in[12];
    const float* og_w_h  = (const float*)d_in[13];
    const float* og_w_x  = (const float*)d_in[14];
    const float* og_b    = (const float*)d_in[15];
    float* out = (float*)d_out;

    timelstm_kernel<<<NBLK, THREADS>>>(
        x, ig_w_c, ig_w_h, ig_w_x, ig_b,
        fg_w_c, fg_w_h, fg_w_x, fg_b,
        in_w_h, in_w_x, in_b,
        og_w_cn, og_w_h, og_w_x, og_b, out);
}

// round 3
// speedup vs baseline: 2.8865x; 2.8865x over previous
#include <cuda_runtime.h>
#include <cstddef>

#define BB 2048
#define NN 512
#define XX 32
#define HH 64
#define TILE_B 8
#define THREADS 128
#define NBLK (BB / TILE_B)   /* 256 */
#define HPITCH 12            /* 48B pitch: 16B-aligned, 4-way bank spread */
#define XPITCH 12
#define GPITCH 65

__device__ __forceinline__ unsigned long long pack2(float v) {
    unsigned long long r;
    asm("mov.b64 %0, {%1, %1};" : "=l"(r) : "f"(v));
    return r;
}
__device__ __forceinline__ unsigned long long fma2(unsigned long long a,
                                                   unsigned long long b,
                                                   unsigned long long c) {
    unsigned long long d;
    asm("fma.rn.f32x2 %0, %1, %2, %3;" : "=l"(d) : "l"(a), "l"(b), "l"(c));
    return d;
}
__device__ __forceinline__ void unpack2(unsigned long long v, float& lo, float& hi) {
    asm("mov.b64 {%0, %1}, %2;" : "=f"(lo), "=f"(hi) : "l"(v));
}

__device__ __forceinline__ float sigmoidf_fast(float x) {
    return __fdividef(1.0f, 1.0f + __expf(-x));
}
__device__ __forceinline__ float tanhf_fast(float x) {
    return __fdividef(2.0f, 1.0f + __expf(-2.0f * x)) - 1.0f;
}

__global__ void __launch_bounds__(THREADS, 2)
timelstm_kernel(const float* __restrict__ x,
                const float* __restrict__ ig_w_c, const float* __restrict__ ig_w_h,
                const float* __restrict__ ig_w_x, const float* __restrict__ ig_b,
                const float* __restrict__ fg_w_c, const float* __restrict__ fg_w_h,
                const float* __restrict__ fg_w_x, const float* __restrict__ fg_b,
                const float* __restrict__ in_w_h, const float* __restrict__ in_w_x,
                const float* __restrict__ in_b,
                const float* __restrict__ og_w_cn, const float* __restrict__ og_w_h,
                const float* __restrict__ og_w_x, const float* __restrict__ og_b,
                float* __restrict__ out)
{
    // h_sh/x_sh: [k][row] (8 rows, pitch 12 floats). One k-row = 32B = 2 LDS.128.
    __shared__ __align__(16) float h_sh[HH * HPITCH];
    __shared__ __align__(16) float x_sh[XX * XPITCH];
    __shared__ float g_sh[4][TILE_B][GPITCH];
    __shared__ float cm_sh[TILE_B][HH];
    __shared__ float wc_sh[3][HH];

    const int tid = threadIdx.x;
    const int b0  = blockIdx.x * TILE_B;
    const int p   = tid >> 6;      // gate pair: 0 -> (ig,fg), 1 -> (in,og)
    const int hid = tid & 63;      // output channel within each gate

    // ---- two full weight rows per thread (k = [x 0..31 | h 0..63]) ----
    const float *Wh0, *Wx0, *Bv0, *Wh1, *Wx1, *Bv1;
    if (p == 0) { Wh0 = ig_w_h; Wx0 = ig_w_x; Bv0 = ig_b;
                  Wh1 = fg_w_h; Wx1 = fg_w_x; Bv1 = fg_b; }
    else        { Wh0 = in_w_h; Wx0 = in_w_x; Bv0 = in_b;
                  Wh1 = og_w_h; Wx1 = og_w_x; Bv1 = og_b; }

    float w0[96], w1[96];
    #pragma unroll
    for (int j = 0; j < 32; j++) { w0[j] = Wx0[hid * XX + j]; w1[j] = Wx1[hid * XX + j]; }
    #pragma unroll
    for (int j = 0; j < 64; j++) { w0[32 + j] = Wh0[hid * HH + j]; w1[32 + j] = Wh1[hid * HH + j]; }
    const float bias0 = Bv0[hid];
    const float bias1 = Bv1[hid];

    if (tid < HH) {
        wc_sh[0][tid] = ig_w_c[tid];
        wc_sh[1][tid] = fg_w_c[tid];
        wc_sh[2][tid] = og_w_cn[tid];
    }
    for (int i = tid; i < HH * HPITCH; i += THREADS) h_sh[i] = 0.0f;
    for (int i = tid; i < TILE_B * HH; i += THREADS) (&cm_sh[0][0])[i] = 0.0f;

    // ---- x prefetch: 2 values/thread/step (8 rows x 32 k = 256) ----
    const int xr = tid >> 5;   // rows xr and xr+4
    const int xk = tid & 31;
    const float* xp0 = x + ((size_t)(b0 + xr) * NN) * XX + xk;
    const float* xp1 = x + ((size_t)(b0 + xr + 4) * NN) * XX + xk;
    float xv0 = xp0[0], xv1 = xp1[0];

    for (int t = 0; t < NN; t++) {
        x_sh[xk * XPITCH + xr]     = xv0;
        x_sh[xk * XPITCH + xr + 4] = xv1;
        __syncthreads();   // x_sh ready AND previous phase-B writes visible

        if (t + 1 < NN) {
            xv0 = xp0[(size_t)(t + 1) * XX];
            xv1 = xp1[(size_t)(t + 1) * XX];
        }

        // ---- phase A: 8 rows x 2 channels, packed f32x2 ----
        unsigned long long a0[4], a1[4];
        {
            unsigned long long b0p = pack2(bias0), b1p = pack2(bias1);
            #pragma unroll
            for (int i = 0; i < 4; i++) { a0[i] = b0p; a1[i] = b1p; }
        }
        #pragma unroll
        for (int k = 0; k < XX; k++) {
            const ulonglong2* ptr = reinterpret_cast<const ulonglong2*>(&x_sh[k * XPITCH]);
            ulonglong2 v0 = ptr[0], v1 = ptr[1];
            unsigned long long u0 = pack2(w0[k]), u1 = pack2(w1[k]);
            a0[0] = fma2(v0.x, u0, a0[0]); a0[1] = fma2(v0.y, u0, a0[1]);
            a0[2] = fma2(v1.x, u0, a0[2]); a0[3] = fma2(v1.y, u0, a0[3]);
            a1[0] = fma2(v0.x, u1, a1[0]); a1[1] = fma2(v0.y, u1, a1[1]);
            a1[2] = fma2(v1.x, u1, a1[2]); a1[3] = fma2(v1.y, u1, a1[3]);
        }
        #pragma unroll
        for (int k = 0; k < HH; k++) {
            const ulonglong2* ptr = reinterpret_cast<const ulonglong2*>(&h_sh[k * HPITCH]);
            ulonglong2 v0 = ptr[0], v1 = ptr[1];
            unsigned long long u0 = pack2(w0[32 + k]), u1 = pack2(w1[32 + k]);
            a0[0] = fma2(v0.x, u0, a0[0]); a0[1] = fma2(v0.y, u0, a0[1]);
            a0[2] = fma2(v1.x, u0, a0[2]); a0[3] = fma2(v1.y, u0, a0[3]);
            a1[0] = fma2(v0.x, u1, a1[0]); a1[1] = fma2(v0.y, u1, a1[1]);
            a1[2] = fma2(v1.x, u1, a1[2]); a1[3] = fma2(v1.y, u1, a1[3]);
        }
        #pragma unroll
        for (int i = 0; i < 4; i++) {
            float lo, hi;
            unpack2(a0[i], lo, hi);
            g_sh[2 * p][2 * i][hid]     = lo;
            g_sh[2 * p][2 * i + 1][hid] = hi;
            unpack2(a1[i], lo, hi);
            g_sh[2 * p + 1][2 * i][hid]     = lo;
            g_sh[2 * p + 1][2 * i + 1][hid] = hi;
        }
        __syncthreads();   // g_sh ready; phase A done reading h_sh/x_sh

        // ---- phase B: 4 elements/thread (rows p, p+2, p+4, p+6; channel hid) ----
        {
            const float wic = wc_sh[0][hid];
            const float wfc = wc_sh[1][hid];
            const float woc = wc_sh[2][hid];
            #pragma unroll
            for (int e = 0; e < 4; e++) {
                const int r = p + 2 * e;
                const float cm  = cm_sh[r][hid];
                const float ig  = sigmoidf_fast(wic * cm + g_sh[0][r][hid]);
                const float fg  = sigmoidf_fast(wfc * cm + g_sh[1][r][hid]);
                const float inn = tanhf_fast(g_sh[2][r][hid]);
                const float cmn = fg * cm + ig * inn;
                const float og  = sigmoidf_fast(woc * cmn + g_sh[3][r][hid]);
                const float hv  = og * tanhf_fast(cmn);
                cm_sh[r][hid] = cmn;
                h_sh[hid * HPITCH + r] = hv;
                if (t == NN - 1)
                    out[(size_t)(b0 + r) * HH + hid] = hv;
            }
        }
        // loop-top barrier orders these writes before the next phase A
    }
}

extern "C" void kernel_launch(void* const* d_in, const int* in_sizes, int n_in,
                              void* d_out, int out_size) {
    const float* x       = (const float*)d_in[0];
    const float* ig_w_c  = (const float*)d_in[1];
    const float* ig_w_h  = (const float*)d_in[2];
    const float* ig_w_x  = (const float*)d_in[3];
    const float* ig_b    = (const float*)d_in[4];
    const float* fg_w_c  = (const float*)d_in[5];
    const float* fg_w_h  = (const float*)d_in[6];
    const float* fg_w_x  = (const float*)d_in[7];
    const float* fg_b    = (const float*)d_in[8];
    const float* in_w_h  = (const float*)d_in[9];
    const float* in_w_x  = (const float*)d_in[10];
    const float* in_b    = (const float*)d_in[11];
    const float* og_w_cn = (const float*)d_in[12];
    const float* og_w_h  = (const float*)d_in[13];
    const float* og_w_x  = (const float*)d_in[14];
    const float* og_b    = (const float*)d_in[15];
    float* out = (float*)d_out;

    timelstm_kernel<<<NBLK, THREADS>>>(
        x, ig_w_c, ig_w_h, ig_w_x, ig_b,
        fg_w_c, fg_w_h, fg_w_x, fg_b,
        in_w_h, in_w_x, in_b,
        og_w_cn, og_w_h, og_w_x, og_b, out);
}

// round 4
// speedup vs baseline: 2.9103x; 1.0082x over previous
#include <cuda_runtime.h>
#include <cstddef>

#define BB 2048
#define NN 512
#define XX 32
#define HH 64
#define TILE_B 8
#define THREADS 128
#define NBLK (BB / TILE_B)   /* 256 */
#define HPITCH 12            /* 48B pitch: 16B-aligned, 4-way bank spread */
#define XPITCH 12
#define GPITCH 65

__device__ __forceinline__ unsigned long long pack2(float v) {
    unsigned long long r;
    asm("mov.b64 %0, {%1, %1};" : "=l"(r) : "f"(v));
    return r;
}
__device__ __forceinline__ unsigned long long fma2(unsigned long long a,
                                                   unsigned long long b,
                                                   unsigned long long c) {
    unsigned long long d;
    asm("fma.rn.f32x2 %0, %1, %2, %3;" : "=l"(d) : "l"(a), "l"(b), "l"(c));
    return d;
}
__device__ __forceinline__ void unpack2(unsigned long long v, float& lo, float& hi) {
    asm("mov.b64 {%0, %1}, %2;" : "=f"(lo), "=f"(hi) : "l"(v));
}

__device__ __forceinline__ float sigmoidf_fast(float x) {
    return __fdividef(1.0f, 1.0f + __expf(-x));
}
__device__ __forceinline__ float tanhf_fast(float x) {
    return __fdividef(2.0f, 1.0f + __expf(-2.0f * x)) - 1.0f;
}

__global__ void __launch_bounds__(THREADS, 2)
timelstm_kernel(const float* __restrict__ x,
                const float* __restrict__ ig_w_c, const float* __restrict__ ig_w_h,
                const float* __restrict__ ig_w_x, const float* __restrict__ ig_b,
                const float* __restrict__ fg_w_c, const float* __restrict__ fg_w_h,
                const float* __restrict__ fg_w_x, const float* __restrict__ fg_b,
                const float* __restrict__ in_w_h, const float* __restrict__ in_w_x,
                const float* __restrict__ in_b,
                const float* __restrict__ og_w_cn, const float* __restrict__ og_w_h,
                const float* __restrict__ og_w_x, const float* __restrict__ og_b,
                float* __restrict__ out)
{
    // h_sh/x_sh: [k][row] (8 rows, pitch 12 floats). One k-row = 32B = 2 LDS.128.
    __shared__ __align__(16) float h_sh[HH * HPITCH];
    __shared__ __align__(16) float x_sh[XX * XPITCH];
    __shared__ float g_sh[4][TILE_B][GPITCH];
    __shared__ float cm_sh[TILE_B][HH];
    __shared__ float wc_sh[3][HH];

    const int tid = threadIdx.x;
    const int b0  = blockIdx.x * TILE_B;
    const int p   = tid >> 6;      // gate pair: 0 -> (ig,fg), 1 -> (in,og)
    const int hid = tid & 63;      // output channel within each gate

    // ---- two full weight rows per thread (k = [x 0..31 | h 0..63]) ----
    const float *Wh0, *Wx0, *Bv0, *Wh1, *Wx1, *Bv1;
    if (p == 0) { Wh0 = ig_w_h; Wx0 = ig_w_x; Bv0 = ig_b;
                  Wh1 = fg_w_h; Wx1 = fg_w_x; Bv1 = fg_b; }
    else        { Wh0 = in_w_h; Wx0 = in_w_x; Bv0 = in_b;
                  Wh1 = og_w_h; Wx1 = og_w_x; Bv1 = og_b; }

    float w0[96], w1[96];
    #pragma unroll
    for (int j = 0; j < 32; j++) { w0[j] = Wx0[hid * XX + j]; w1[j] = Wx1[hid * XX + j]; }
    #pragma unroll
    for (int j = 0; j < 64; j++) { w0[32 + j] = Wh0[hid * HH + j]; w1[32 + j] = Wh1[hid * HH + j]; }
    const float bias0 = Bv0[hid];
    const float bias1 = Bv1[hid];

    if (tid < HH) {
        wc_sh[0][tid] = ig_w_c[tid];
        wc_sh[1][tid] = fg_w_c[tid];
        wc_sh[2][tid] = og_w_cn[tid];
    }
    for (int i = tid; i < HH * HPITCH; i += THREADS) h_sh[i] = 0.0f;
    for (int i = tid; i < TILE_B * HH; i += THREADS) (&cm_sh[0][0])[i] = 0.0f;

    // ---- x prefetch: 2 values/thread/step (8 rows x 32 k = 256) ----
    const int xr = tid >> 5;   // rows xr and xr+4
    const int xk = tid & 31;
    const float* xp0 = x + ((size_t)(b0 + xr) * NN) * XX + xk;
    const float* xp1 = x + ((size_t)(b0 + xr + 4) * NN) * XX + xk;
    float xv0 = xp0[0], xv1 = xp1[0];

    for (int t = 0; t < NN; t++) {
        x_sh[xk * XPITCH + xr]     = xv0;
        x_sh[xk * XPITCH + xr + 4] = xv1;
        __syncthreads();   // x_sh ready AND previous phase-B writes visible

        if (t + 1 < NN) {
            xv0 = xp0[(size_t)(t + 1) * XX];
            xv1 = xp1[(size_t)(t + 1) * XX];
        }

        // ---- phase A: 8 rows x 2 channels, packed f32x2 ----
        unsigned long long a0[4], a1[4];
        {
            unsigned long long b0p = pack2(bias0), b1p = pack2(bias1);
            #pragma unroll
            for (int i = 0; i < 4; i++) { a0[i] = b0p; a1[i] = b1p; }
        }
        #pragma unroll
        for (int k = 0; k < XX; k++) {
            const ulonglong2* ptr = reinterpret_cast<const ulonglong2*>(&x_sh[k * XPITCH]);
            ulonglong2 v0 = ptr[0], v1 = ptr[1];
            unsigned long long u0 = pack2(w0[k]), u1 = pack2(w1[k]);
            a0[0] = fma2(v0.x, u0, a0[0]); a0[1] = fma2(v0.y, u0, a0[1]);
            a0[2] = fma2(v1.x, u0, a0[2]); a0[3] = fma2(v1.y, u0, a0[3]);
            a1[0] = fma2(v0.x, u1, a1[0]); a1[1] = fma2(v0.y, u1, a1[1]);
            a1[2] = fma2(v1.x, u1, a1[2]); a1[3] = fma2(v1.y, u1, a1[3]);
        }
        #pragma unroll
        for (int k = 0; k < HH; k++) {
            const ulonglong2* ptr = reinterpret_cast<const ulonglong2*>(&h_sh[k * HPITCH]);
            ulonglong2 v0 = ptr[0], v1 = ptr[1];
            unsigned long long u0 = pack2(w0[32 + k]), u1 = pack2(w1[32 + k]);
            a0[0] = fma2(v0.x, u0, a0[0]); a0[1] = fma2(v0.y, u0, a0[1]);
            a0[2] = fma2(v1.x, u0, a0[2]); a0[3] = fma2(v1.y, u0, a0[3]);
            a1[0] = fma2(v0.x, u1, a1[0]); a1[1] = fma2(v0.y, u1, a1[1]);
            a1[2] = fma2(v1.x, u1, a1[2]); a1[3] = fma2(v1.y, u1, a1[3]);
        }
        #pragma unroll
        for (int i = 0; i < 4; i++) {
            float lo, hi;
            unpack2(a0[i], lo, hi);
            g_sh[2 * p][2 * i][hid]     = lo;
            g_sh[2 * p][2 * i + 1][hid] = hi;
            unpack2(a1[i], lo, hi);
            g_sh[2 * p + 1][2 * i][hid]     = lo;
            g_sh[2 * p + 1][2 * i + 1][hid] = hi;
        }
        __syncthreads();   // g_sh ready; phase A done reading h_sh/x_sh

        // ---- phase B: 4 elements/thread (rows p, p+2, p+4, p+6; channel hid) ----
        {
            const float wic = wc_sh[0][hid];
            const float wfc = wc_sh[1][hid];
            const float woc = wc_sh[2][hid];
            #pragma unroll
            for (int e = 0; e < 4; e++) {
                const int r = p + 2 * e;
                const float cm  = cm_sh[r][hid];
                const float ig  = sigmoidf_fast(wic * cm + g_sh[0][r][hid]);
                const float fg  = sigmoidf_fast(wfc * cm + g_sh[1][r][hid]);
                const float inn = tanhf_fast(g_sh[2][r][hid]);
                const float cmn = fg * cm + ig * inn;
                const float og  = sigmoidf_fast(woc * cmn + g_sh[3][r][hid]);
                const float hv  = og * tanhf_fast(cmn);
                cm_sh[r][hid] = cmn;
                h_sh[hid * HPITCH + r] = hv;
                if (t == NN - 1)
                    out[(size_t)(b0 + r) * HH + hid] = hv;
            }
        }
        // loop-top barrier orders these writes before the next phase A
    }
}

extern "C" void kernel_launch(void* const* d_in, const int* in_sizes, int n_in,
                              void* d_out, int out_size) {
    const float* x       = (const float*)d_in[0];
    const float* ig_w_c  = (const float*)d_in[1];
    const float* ig_w_h  = (const float*)d_in[2];
    const float* ig_w_x  = (const float*)d_in[3];
    const float* ig_b    = (const float*)d_in[4];
    const float* fg_w_c  = (const float*)d_in[5];
    const float* fg_w_h  = (const float*)d_in[6];
    const float* fg_w_x  = (const float*)d_in[7];
    const float* fg_b    = (const float*)d_in[8];
    const float* in_w_h  = (const float*)d_in[9];
    const float* in_w_x  = (const float*)d_in[10];
    const float* in_b    = (const float*)d_in[11];
    const float* og_w_cn = (const float*)d_in[12];
    const float* og_w_h  = (const float*)d_in[13];
    const float* og_w_x  = (const float*)d_in[14];
    const float* og_b    = (const float*)d_in[15];
    float* out = (float*)d_out;

    timelstm_kernel<<<NBLK, THREADS>>>(
        x, ig_w_c, ig_w_h, ig_w_x, ig_b,
        fg_w_c, fg_w_h, fg_w_x, fg_b,
        in_w_h, in_w_x, in_b,
        og_w_cn, og_w_h, og_w_x, og_b, out);
}